// round 2
// baseline (speedup 1.0000x reference)
#include <cuda_runtime.h>
#include <math.h>

#define CIN 32
#define COUT 64
#define NWEIGHT (125 * CIN * COUT)

// Weight transposed to [kd*25+kh*5+kw][cin][cout] so consecutive couts are contiguous.
__device__ float g_wt[NWEIGHT];

__global__ void wt_transpose_kernel(const float* __restrict__ w) {
    int i = blockIdx.x * blockDim.x + threadIdx.x;
    if (i >= NWEIGHT) return;
    int cout = i & 63;
    int cin  = (i >> 6) & 31;
    int kk   = i >> 11;               // 0..124
    g_wt[i] = w[(cin * COUT + cout) * 125 + kk];
}

// Process one kd tap-plane: 25 (kh,kw) taps, each contributing to a 3x3 set of
// the 6x6 (oh,ow) accumulators (parity-matched gather of stride-2 transposed conv).
__device__ __forceinline__ void process_kd(
    const int kd, const int l_d, const int cin, const int cout,
    const float* __restrict__ xs, float acc[6][6])
{
    const int id_l = (l_d + 4 - kd) >> 1;             // in [0,4]
    const float* sp = xs + cin * 125 + id_l * 25;
    float s[25];
#pragma unroll
    for (int q = 0; q < 25; ++q) s[q] = sp[q];        // warp-uniform broadcast LDS

    const float* wp = g_wt + ((kd * 25) * CIN + cin) * COUT + cout;
#pragma unroll
    for (int kh = 0; kh < 5; ++kh) {
        const int jh = 2 - (kh >> 1);
        const int ph = kh & 1;
#pragma unroll
        for (int kw = 0; kw < 5; ++kw) {
            const int jw = 2 - (kw >> 1);
            const int pw = kw & 1;
            const float wv = wp[(kh * 5 + kw) * (CIN * COUT)];  // coalesced over cout
#pragma unroll
            for (int j = 0; j < 3; ++j)
#pragma unroll
                for (int i = 0; i < 3; ++i)
                    acc[ph + 2 * j][pw + 2 * i] =
                        fmaf(wv, s[(jh + j) * 5 + (jw + i)],
                             acc[ph + 2 * j][pw + 2 * i]);
        }
    }
}

__global__ __launch_bounds__(384)
void fused_kernel(const float* __restrict__ x,
                  const float* __restrict__ bias,
                  float* __restrict__ out)
{
    __shared__ float xs[CIN * 125];       // input patch [cin][5][5][5]
    __shared__ float red[6 * 64 + 2];     // reduction scratch

    const int b   = blockIdx.x;           // 8000 = 16 * 5 * 10 * 10
    const int n   = b / 500;
    const int r   = b % 500;
    const int odc = r / 100;
    const int ohc = (r / 10) % 10;
    const int owc = r % 10;

    const int tid  = threadIdx.x;         // 384 = 64 cout x 6 l_d
    const int cout = tid & 63;
    const int l_d  = tid >> 6;

    const int id0 = 3 * odc - 1;
    const int ih0 = 3 * ohc - 1;
    const int iw0 = 3 * owc - 1;

    // Stage 5x5x5 input patch for all 32 cin (zero-fill the -1 halo).
    for (int t = tid; t < CIN * 125; t += 384) {
        const int cin = t / 125;
        const int rr  = t % 125;
        const int dl  = rr / 25;
        const int hl  = (rr / 5) % 5;
        const int wl  = rr % 5;
        const int id = id0 + dl, ih = ih0 + hl, iw = iw0 + wl;
        float v = 0.f;
        if (id >= 0 && ih >= 0 && iw >= 0)   // upper bounds always in range
            v = x[(((n * CIN + cin) * 16 + id) << 10) + (ih << 5) + iw];
        xs[t] = v;
    }
    __syncthreads();

    float acc[6][6];
#pragma unroll
    for (int a = 0; a < 6; ++a)
#pragma unroll
        for (int c = 0; c < 6; ++c) acc[a][c] = 0.f;

    const bool odd = (l_d & 1);
    for (int cin = 0; cin < CIN; ++cin) {
        if (!odd) {
            process_kd(0, l_d, cin, cout, xs, acc);
            process_kd(2, l_d, cin, cout, xs, acc);
            process_kd(4, l_d, cin, cout, xs, acc);
        } else {
            process_kd(1, l_d, cin, cout, xs, acc);
            process_kd(3, l_d, cin, cout, xs, acc);
        }
    }

    // max over this thread's 6x6 (oh,ow) slab
    float m = -INFINITY;
#pragma unroll
    for (int a = 0; a < 6; ++a)
#pragma unroll
        for (int c = 0; c < 6; ++c) m = fmaxf(m, acc[a][c]);

    red[l_d * 64 + cout] = m;
    __syncthreads();

    if (tid < 64) {
        // max over l_d, add bias, then sum over the 64 channels
        float v = red[tid];
#pragma unroll
        for (int l = 1; l < 6; ++l) v = fmaxf(v, red[l * 64 + tid]);
        v += bias[tid];
#pragma unroll
        for (int o = 16; o > 0; o >>= 1)
            v += __shfl_down_sync(0xffffffffu, v, o);
        if ((tid & 31) == 0) red[6 * 64 + (tid >> 5)] = v;
    }
    __syncthreads();
    if (tid == 0) out[b] = red[6 * 64] + red[6 * 64 + 1];
}

extern "C" void kernel_launch(void* const* d_in, const int* in_sizes, int n_in,
                              void* d_out, int out_size) {
    const float* x    = (const float*)d_in[0];
    const float* w    = (const float*)d_in[1];
    const float* bias = (const float*)d_in[2];
    float* out = (float*)d_out;

    wt_transpose_kernel<<<(NWEIGHT + 255) / 256, 256>>>(w);
    fused_kernel<<<8000, 384>>>(x, bias, out);
}

// round 3
// speedup vs baseline: 1.1326x; 1.1326x over previous
#include <cuda_runtime.h>
#include <math.h>

#define CIN 32
#define COUT 64
// Packed weight layout: [kd][kh][p(3)][cin][cout] of float2 (kw=2p, kw=2p+1; p=2 hi = 0)
#define NWP (5 * 5 * 3 * CIN * COUT)

__device__ unsigned long long g_wt2[NWP];

typedef unsigned long long u64;

__global__ void wt_pack_kernel(const float* __restrict__ w) {
    int i = blockIdx.x * blockDim.x + threadIdx.x;
    if (i >= NWP) return;
    int cout = i & 63;
    int cin  = (i >> 6) & 31;
    int t    = i >> 11;            // kd*15 + kh*3 + p
    int p    = t % 3;
    int kh   = (t / 3) % 5;
    int kd   = t / 15;
    const float* src = w + (cin * COUT + cout) * 125 + kd * 25 + kh * 5;
    float lo = src[2 * p];
    float hi = (p < 2) ? src[2 * p + 1] : 0.f;
    g_wt2[i] = ((u64)__float_as_uint(hi) << 32) | (u64)__float_as_uint(lo);
}

__device__ __forceinline__ void fma2(u64& d, u64 a, u64 b) {
    asm("fma.rn.f32x2 %0, %1, %2, %0;" : "+l"(d) : "l"(a), "l"(b));
}

// One kd tap-plane: 5 kh x 3 kw-pairs, each pair -> 9 packed FMAs (3 j-rows x 3 col-pairs).
__device__ __forceinline__ void process_kd(
    const int kd, const int l_d, const int cin, const int cout,
    const u64* __restrict__ xs2, u64 acc[6][3])
{
    const int id_l = (l_d + 4 - kd) >> 1;               // in [0,4]
    const u64* sp = xs2 + cin * 125 + id_l * 25;
    u64 s[25];
#pragma unroll
    for (int q = 0; q < 25; ++q) s[q] = sp[q];          // LDS.64 broadcast (s,s)

    const u64* wp = g_wt2 + (kd * 15) * (CIN * COUT) + cin * COUT + cout;
#pragma unroll
    for (int kh = 0; kh < 5; ++kh) {
        const int jh = 2 - (kh >> 1);
        const int ph = kh & 1;
#pragma unroll
        for (int p = 0; p < 3; ++p) {
            const int jw = 2 - p;
            const u64 w2 = __ldg(wp + (kh * 3 + p) * (CIN * COUT));
#pragma unroll
            for (int j = 0; j < 3; ++j)
#pragma unroll
                for (int i = 0; i < 3; ++i)
                    fma2(acc[ph + 2 * j][i], w2, s[(jh + j) * 5 + jw + i]);
        }
    }
}

__global__ __launch_bounds__(384)
void fused_kernel(const float* __restrict__ x,
                  const float* __restrict__ bias,
                  float* __restrict__ out)
{
    __shared__ u64   xs2[CIN * 125];      // input patch duplicated (v,v)
    __shared__ float red[6 * 64 + 2];

    const int b   = blockIdx.x;           // 8000 = 16 * 5 * 10 * 10
    const int n   = b / 500;
    const int r   = b % 500;
    const int odc = r / 100;
    const int ohc = (r / 10) % 10;
    const int owc = r % 10;

    const int tid  = threadIdx.x;         // 384 = 64 cout x 6 l_d
    const int cout = tid & 63;
    const int l_d  = tid >> 6;

    const int id0 = 3 * odc - 1;
    const int ih0 = 3 * ohc - 1;
    const int iw0 = 3 * owc - 1;

    for (int t = tid; t < CIN * 125; t += 384) {
        const int cin = t / 125;
        const int rr  = t % 125;
        const int dl  = rr / 25;
        const int hl  = (rr / 5) % 5;
        const int wl  = rr % 5;
        const int id = id0 + dl, ih = ih0 + hl, iw = iw0 + wl;
        float v = 0.f;
        if (id >= 0 && ih >= 0 && iw >= 0)     // upper bounds always in range
            v = x[(((n * CIN + cin) * 16 + id) << 10) + (ih << 5) + iw];
        const u64 bv = (u64)__float_as_uint(v);
        xs2[t] = (bv << 32) | bv;
    }
    __syncthreads();

    u64 acc[6][3];
#pragma unroll
    for (int a = 0; a < 6; ++a)
#pragma unroll
        for (int c = 0; c < 3; ++c) acc[a][c] = 0ull;

    if (!(l_d & 1)) {
#pragma unroll 1
        for (int cin = 0; cin < CIN; ++cin) {
            process_kd(0, l_d, cin, cout, xs2, acc);
            process_kd(2, l_d, cin, cout, xs2, acc);
            process_kd(4, l_d, cin, cout, xs2, acc);
        }
    } else {
#pragma unroll 1
        for (int cin = 0; cin < CIN; ++cin) {
            process_kd(1, l_d, cin, cout, xs2, acc);
            process_kd(3, l_d, cin, cout, xs2, acc);
        }
    }

    // max over this thread's 6x6 (oh,ow) slab (unpack f32x2 pairs)
    float m = -INFINITY;
#pragma unroll
    for (int a = 0; a < 6; ++a)
#pragma unroll
        for (int c = 0; c < 3; ++c) {
            m = fmaxf(m, __uint_as_float((unsigned)(acc[a][c] & 0xffffffffu)));
            m = fmaxf(m, __uint_as_float((unsigned)(acc[a][c] >> 32)));
        }

    red[l_d * 64 + cout] = m;
    __syncthreads();

    if (tid < 64) {
        float v = red[tid];
#pragma unroll
        for (int l = 1; l < 6; ++l) v = fmaxf(v, red[l * 64 + tid]);
        v += bias[tid];
#pragma unroll
        for (int o = 16; o > 0; o >>= 1)
            v += __shfl_down_sync(0xffffffffu, v, o);
        if ((tid & 31) == 0) red[6 * 64 + (tid >> 5)] = v;
    }
    __syncthreads();
    if (tid == 0) out[b] = red[6 * 64] + red[6 * 64 + 1];
}

extern "C" void kernel_launch(void* const* d_in, const int* in_sizes, int n_in,
                              void* d_out, int out_size) {
    const float* x    = (const float*)d_in[0];
    const float* w    = (const float*)d_in[1];
    const float* bias = (const float*)d_in[2];
    float* out = (float*)d_out;

    wt_pack_kernel<<<(NWP + 255) / 256, 256>>>(w);
    fused_kernel<<<8000, 384>>>(x, bias, out);
}

// round 4
// speedup vs baseline: 1.1353x; 1.0024x over previous
#include <cuda_runtime.h>
#include <math.h>

#define CIN 32
#define COUT 64
// Packed weight layout: [kd][kh][p(3)][cin][cout] of float2 (kw=2p, kw=2p+1; p=2 hi = 0)
#define NWP (5 * 5 * 3 * CIN * COUT)

__device__ unsigned long long g_wt2[NWP];

typedef unsigned long long u64;

__global__ void wt_pack_kernel(const float* __restrict__ w) {
    int i = blockIdx.x * blockDim.x + threadIdx.x;
    if (i >= NWP) return;
    int cout = i & 63;
    int cin  = (i >> 6) & 31;
    int t    = i >> 11;            // kd*15 + kh*3 + p
    int p    = t % 3;
    int kh   = (t / 3) % 5;
    int kd   = t / 15;
    const float* src = w + (cin * COUT + cout) * 125 + kd * 25 + kh * 5;
    float lo = src[2 * p];
    float hi = (p < 2) ? src[2 * p + 1] : 0.f;
    g_wt2[i] = ((u64)__float_as_uint(hi) << 32) | (u64)__float_as_uint(lo);
}

__device__ __forceinline__ void fma2(u64& d, u64 a, u64 b) {
    asm("fma.rn.f32x2 %0, %1, %2, %0;" : "+l"(d) : "l"(a), "l"(b));
}

// One kd tap-plane: 5 kh x 3 kw-pairs, each pair -> 9 packed FMAs (3 j-rows x 3 col-pairs).
__device__ __forceinline__ void process_kd(
    const int kd, const int l_d, const int cin, const int cout,
    const u64* __restrict__ xs2, u64 acc[6][3])
{
    const int id_l = (l_d + 4 - kd) >> 1;               // in [0,4]
    const u64* sp = xs2 + cin * 125 + id_l * 25;
    u64 s[25];
#pragma unroll
    for (int q = 0; q < 25; ++q) s[q] = sp[q];          // LDS.64 broadcast (s,s)

    const u64* wp = g_wt2 + (kd * 15) * (CIN * COUT) + cin * COUT + cout;
#pragma unroll
    for (int kh = 0; kh < 5; ++kh) {
        const int jh = 2 - (kh >> 1);
        const int ph = kh & 1;
#pragma unroll
        for (int p = 0; p < 3; ++p) {
            const int jw = 2 - p;
            const u64 w2 = __ldg(wp + (kh * 3 + p) * (CIN * COUT));
#pragma unroll
            for (int j = 0; j < 3; ++j)
#pragma unroll
                for (int i = 0; i < 3; ++i)
                    fma2(acc[ph + 2 * j][i], w2, s[(jh + j) * 5 + jw + i]);
        }
    }
}

__global__ __launch_bounds__(384, 2)
void fused_kernel(const float* __restrict__ x,
                  const float* __restrict__ bias,
                  float* __restrict__ out)
{
    __shared__ u64   xs2[CIN * 125];      // input patch duplicated (v,v)
    __shared__ float red[6 * 64 + 2];

    const int b   = blockIdx.x;           // 8000 = 16 * 5 * 10 * 10
    const int n   = b / 500;
    const int r   = b % 500;
    const int odc = r / 100;
    const int ohc = (r / 10) % 10;
    const int owc = r % 10;

    const int tid  = threadIdx.x;         // 384 threads = 12 warps
    const int wid  = tid >> 5;
    const int lane = tid & 31;
    // SMSP-balancing permutation: warp-pair p -> l_d so each SMSP gets a
    // mix of even (3 kd planes) and odd (2 kd planes) parity warps.
    const int p_   = wid >> 1;
    const int l_d  = ((p_ & 1) ? 3 : 0) + (p_ >> 1);
    const int cout = ((wid & 1) << 5) | lane;

    const int id0 = 3 * odc - 1;
    const int ih0 = 3 * ohc - 1;
    const int iw0 = 3 * owc - 1;

    for (int t = tid; t < CIN * 125; t += 384) {
        const int cin = t / 125;
        const int rr  = t % 125;
        const int dl  = rr / 25;
        const int hl  = (rr / 5) % 5;
        const int wl  = rr % 5;
        const int id = id0 + dl, ih = ih0 + hl, iw = iw0 + wl;
        float v = 0.f;
        if (id >= 0 && ih >= 0 && iw >= 0)     // upper bounds always in range
            v = x[(((n * CIN + cin) * 16 + id) << 10) + (ih << 5) + iw];
        const u64 bv = (u64)__float_as_uint(v);
        xs2[t] = (bv << 32) | bv;
    }
    __syncthreads();

    u64 acc[6][3];
#pragma unroll
    for (int a = 0; a < 6; ++a)
#pragma unroll
        for (int c = 0; c < 3; ++c) acc[a][c] = 0ull;

    if (!(l_d & 1)) {
#pragma unroll 1
        for (int cin = 0; cin < CIN; ++cin) {
            process_kd(0, l_d, cin, cout, xs2, acc);
            process_kd(2, l_d, cin, cout, xs2, acc);
            process_kd(4, l_d, cin, cout, xs2, acc);
        }
    } else {
#pragma unroll 1
        for (int cin = 0; cin < CIN; ++cin) {
            process_kd(1, l_d, cin, cout, xs2, acc);
            process_kd(3, l_d, cin, cout, xs2, acc);
        }
    }

    // max over this thread's 6x6 (oh,ow) slab (unpack f32x2 pairs)
    float m = -INFINITY;
#pragma unroll
    for (int a = 0; a < 6; ++a)
#pragma unroll
        for (int c = 0; c < 3; ++c) {
            m = fmaxf(m, __uint_as_float((unsigned)(acc[a][c] & 0xffffffffu)));
            m = fmaxf(m, __uint_as_float((unsigned)(acc[a][c] >> 32)));
        }

    red[l_d * 64 + cout] = m;
    __syncthreads();

    if (tid < 64) {
        float v = red[tid];
#pragma unroll
        for (int l = 1; l < 6; ++l) v = fmaxf(v, red[l * 64 + tid]);
        v += bias[tid];
#pragma unroll
        for (int o = 16; o > 0; o >>= 1)
            v += __shfl_down_sync(0xffffffffu, v, o);
        if ((tid & 31) == 0) red[6 * 64 + (tid >> 5)] = v;
    }
    __syncthreads();
    if (tid == 0) out[b] = red[6 * 64] + red[6 * 64 + 1];
}

extern "C" void kernel_launch(void* const* d_in, const int* in_sizes, int n_in,
                              void* d_out, int out_size) {
    const float* x    = (const float*)d_in[0];
    const float* w    = (const float*)d_in[1];
    const float* bias = (const float*)d_in[2];
    float* out = (float*)d_out;

    wt_pack_kernel<<<(NWP + 255) / 256, 256>>>(w);
    fused_kernel<<<8000, 384>>>(x, bias, out);
}

// round 5
// speedup vs baseline: 1.1353x; 1.0000x over previous
#include <cuda_runtime.h>
#include <math.h>

#define CIN 32
#define COUT 64
// Packed weight layout: [kd][kh][p(3)][cin][cout] of float2 (kw=2p, kw=2p+1; p=2 hi = 0)
#define NWP (5 * 5 * 3 * CIN * COUT)

__device__ unsigned long long g_wt2[NWP];

typedef unsigned long long u64;

__global__ void wt_pack_kernel(const float* __restrict__ w) {
    int i = blockIdx.x * blockDim.x + threadIdx.x;
    if (i >= NWP) return;
    int cout = i & 63;
    int cin  = (i >> 6) & 31;
    int t    = i >> 11;            // kd*15 + kh*3 + p
    int p    = t % 3;
    int kh   = (t / 3) % 5;
    int kd   = t / 15;
    const float* src = w + (cin * COUT + cout) * 125 + kd * 25 + kh * 5;
    float lo = src[2 * p];
    float hi = (p < 2) ? src[2 * p + 1] : 0.f;
    g_wt2[i] = ((u64)__float_as_uint(hi) << 32) | (u64)__float_as_uint(lo);
}

__device__ __forceinline__ void fma2(u64& d, u64 a, u64 b) {
    asm("fma.rn.f32x2 %0, %1, %2, %0;" : "+l"(d) : "l"(a), "l"(b));
}

// One kd tap-plane: 5 kh x 3 kw-pairs, each pair -> 9 packed FMAs (3 j-rows x 3 col-pairs).
__device__ __forceinline__ void process_kd(
    const int kd, const int l_d, const int cin, const int cout,
    const u64* __restrict__ xs2, u64 acc[6][3])
{
    const int id_l = (l_d + 4 - kd) >> 1;               // in [0,4]
    const u64* sp = xs2 + cin * 125 + id_l * 25;
    u64 s[25];
#pragma unroll
    for (int q = 0; q < 25; ++q) s[q] = sp[q];          // LDS.64 broadcast (s,s)

    const u64* wp = g_wt2 + (kd * 15) * (CIN * COUT) + cin * COUT + cout;
#pragma unroll
    for (int kh = 0; kh < 5; ++kh) {
        const int jh = 2 - (kh >> 1);
        const int ph = kh & 1;
#pragma unroll
        for (int p = 0; p < 3; ++p) {
            const int jw = 2 - p;
            const u64 w2 = __ldg(wp + (kh * 3 + p) * (CIN * COUT));
#pragma unroll
            for (int j = 0; j < 3; ++j)
#pragma unroll
                for (int i = 0; i < 3; ++i)
                    fma2(acc[ph + 2 * j][i], w2, s[(jh + j) * 5 + jw + i]);
        }
    }
}

__global__ __launch_bounds__(384, 2)
void fused_kernel(const float* __restrict__ x,
                  const float* __restrict__ bias,
                  float* __restrict__ out)
{
    __shared__ u64   xs2[CIN * 125];      // input patch duplicated (v,v)
    __shared__ float red[6 * 64 + 2];

    const int b   = blockIdx.x;           // 8000 = 16 * 5 * 10 * 10
    const int n   = b / 500;
    const int r   = b % 500;
    const int odc = r / 100;
    const int ohc = (r / 10) % 10;
    const int owc = r % 10;

    const int tid  = threadIdx.x;         // 384 threads = 12 warps
    const int wid  = tid >> 5;
    const int lane = tid & 31;
    // SMSP-balancing permutation: warp-pair p -> l_d so each SMSP gets a
    // mix of even (3 kd planes) and odd (2 kd planes) parity warps.
    const int p_   = wid >> 1;
    const int l_d  = ((p_ & 1) ? 3 : 0) + (p_ >> 1);
    const int cout = ((wid & 1) << 5) | lane;

    const int id0 = 3 * odc - 1;
    const int ih0 = 3 * ohc - 1;
    const int iw0 = 3 * owc - 1;

    for (int t = tid; t < CIN * 125; t += 384) {
        const int cin = t / 125;
        const int rr  = t % 125;
        const int dl  = rr / 25;
        const int hl  = (rr / 5) % 5;
        const int wl  = rr % 5;
        const int id = id0 + dl, ih = ih0 + hl, iw = iw0 + wl;
        float v = 0.f;
        if (id >= 0 && ih >= 0 && iw >= 0)     // upper bounds always in range
            v = x[(((n * CIN + cin) * 16 + id) << 10) + (ih << 5) + iw];
        const u64 bv = (u64)__float_as_uint(v);
        xs2[t] = (bv << 32) | bv;
    }
    __syncthreads();

    u64 acc[6][3];
#pragma unroll
    for (int a = 0; a < 6; ++a)
#pragma unroll
        for (int c = 0; c < 3; ++c) acc[a][c] = 0ull;

    if (!(l_d & 1)) {
#pragma unroll 1
        for (int cin = 0; cin < CIN; ++cin) {
            process_kd(0, l_d, cin, cout, xs2, acc);
            process_kd(2, l_d, cin, cout, xs2, acc);
            process_kd(4, l_d, cin, cout, xs2, acc);
        }
    } else {
#pragma unroll 1
        for (int cin = 0; cin < CIN; ++cin) {
            process_kd(1, l_d, cin, cout, xs2, acc);
            process_kd(3, l_d, cin, cout, xs2, acc);
        }
    }

    // max over this thread's 6x6 (oh,ow) slab (unpack f32x2 pairs)
    float m = -INFINITY;
#pragma unroll
    for (int a = 0; a < 6; ++a)
#pragma unroll
        for (int c = 0; c < 3; ++c) {
            m = fmaxf(m, __uint_as_float((unsigned)(acc[a][c] & 0xffffffffu)));
            m = fmaxf(m, __uint_as_float((unsigned)(acc[a][c] >> 32)));
        }

    red[l_d * 64 + cout] = m;
    __syncthreads();

    if (tid < 64) {
        float v = red[tid];
#pragma unroll
        for (int l = 1; l < 6; ++l) v = fmaxf(v, red[l * 64 + tid]);
        v += bias[tid];
#pragma unroll
        for (int o = 16; o > 0; o >>= 1)
            v += __shfl_down_sync(0xffffffffu, v, o);
        if ((tid & 31) == 0) red[6 * 64 + (tid >> 5)] = v;
    }
    __syncthreads();
    if (tid == 0) out[b] = red[6 * 64] + red[6 * 64 + 1];
}

extern "C" void kernel_launch(void* const* d_in, const int* in_sizes, int n_in,
                              void* d_out, int out_size) {
    const float* x    = (const float*)d_in[0];
    const float* w    = (const float*)d_in[1];
    const float* bias = (const float*)d_in[2];
    float* out = (float*)d_out;

    wt_pack_kernel<<<(NWP + 255) / 256, 256>>>(w);
    fused_kernel<<<8000, 384>>>(x, bias, out);
}